// round 16
// baseline (speedup 1.0000x reference)
#include <cuda_runtime.h>
#include <math.h>

#define NB 16
#define NN 1024
#define NTOT 16384
#define NMASK 16383
#define NE 262144
#define CIN 64
#define HID 32
#define K1 100
#define K1P 128
#define K2 16
#define COUT 10
#define DMAX 64
#define EPSL 1e-15f
#define FULL 0xffffffffu

// ---------------- scratch (device globals; zero-initialized at load; self-cleaned) ----------------
__device__ float g_h1[NTOT*HID];
__device__ float g_s1[NTOT*K1P];     // 128-stride rows, tail zeroed
__device__ float g_sq1[NTOT];
__device__ float g_dist[NTOT*DMAX];  // edge1: dist ; after mid: final weight w
__device__ float g_invd[NTOT];
__device__ float g_h2[NTOT*HID];
__device__ float g_s2[NTOT*K2];
__device__ float g_Y[NTOT*K2];
__device__ float g_fro2[NB];         // sum-of-squares of S1^T S1 per batch
__device__ float g_SS2[NB*K2*K2];
__device__ float g_outp[NB*K2*HID];
__device__ float g_outadj[NB*K2*K2];
__device__ float g_sas[NB], g_sds[NB], g_tr1[NB], g_tr2[NB], g_den[NB];
__device__ int   g_cnt[NTOT];
__device__ int   g_edst[NTOT*DMAX];

// ---------------- fused: edge bucketing (blocks 0..1023) + node pass 1 ----------------
__global__ void front_kernel(const int* __restrict__ src, const int* __restrict__ dst,
                             const float* __restrict__ x, const float* __restrict__ w1,
                             const float* __restrict__ b1, const float* __restrict__ pw,
                             const float* __restrict__ pb){
    if(blockIdx.x < 1024){
        int e = blockIdx.x*256 + threadIdx.x;
        int s = src[e] & NMASK;
        int slot = atomicAdd(&g_cnt[s], 1);
        if(slot < DMAX) g_edst[s*DMAX + slot] = dst[e] & NMASK;
        return;
    }
    int n    = ((blockIdx.x-1024)*256 + threadIdx.x)>>5;
    int lane = threadIdx.x & 31;
    if(n>=NTOT) return;
    int l3i = lane & 3;
    float x0 = x[n*CIN+lane], x1 = x[n*CIN+32+lane];
    float h = b1[lane];
    #pragma unroll
    for(int c=0;c<32;c++) h += __shfl_sync(FULL,x0,c)*w1[c*HID+lane];
    #pragma unroll
    for(int c=0;c<32;c++) h += __shfl_sync(FULL,x1,c)*w1[(32+c)*HID+lane];
    g_h1[n*HID+lane] = h;
    float l0=pb[lane], l1=pb[lane+32], l2=pb[lane+64];
    float pb3 = pb[96+l3i];
    float l3 = (lane<4)? pb3 : -1e30f;
    #pragma unroll
    for(int c=0;c<32;c++){
        float hv = __shfl_sync(FULL,h,c);
        l0 += hv*pw[c*K1+lane];
        l1 += hv*pw[c*K1+lane+32];
        l2 += hv*pw[c*K1+lane+64];
        l3 += hv*pw[c*K1+96+l3i];
    }
    float m = fmaxf(fmaxf(l0,l1),fmaxf(l2,l3));
    for(int o=16;o;o>>=1) m = fmaxf(m, __shfl_xor_sync(FULL,m,o));
    float e0=expf(l0-m), e1=expf(l1-m), e2=expf(l2-m);
    float e3 = (lane<4)? expf(l3-m) : 0.f;
    float s = e0+e1+e2+e3;
    for(int o=16;o;o>>=1) s += __shfl_xor_sync(FULL,s,o);
    float inv = 1.f/s;
    e0*=inv; e1*=inv; e2*=inv; e3*=inv;
    g_s1[n*K1P+lane]=e0; g_s1[n*K1P+lane+32]=e1; g_s1[n*K1P+lane+64]=e2;
    g_s1[n*K1P+96+lane] = (lane<4)? e3 : 0.f;
    float sq = e0*e0+e1*e1+e2*e2+e3*e3;
    for(int o=16;o;o>>=1) sq += __shfl_xor_sync(FULL,sq,o);
    if(lane==0) g_sq1[n]=sq;
}

// ---------------- edge pass 1: 4-edge-unrolled dist+dot; invd inline; sas/sds/tr1 ----------------
__global__ void edge1_kernel(){
    __shared__ float sas_sh, sds_sh, tr1_sh;
    if(threadIdx.x==0){ sas_sh=0.f; sds_sh=0.f; tr1_sh=0.f; }
    __syncthreads();
    int n    = (blockIdx.x*blockDim.x + threadIdx.x)>>5;
    int lane = threadIdx.x & 31;
    if(n<NTOT){
        float4 a = ((const float4*)(g_s1 + n*K1P))[lane];
        float sqn = g_sq1[n];
        int cnt = g_cnt[n]; if(cnt>DMAX) cnt=DMAX; if(cnt<0) cnt=0;
        int base = n*DMAX;
        float rsum=0.f, dsum=0.f;
        int j=0;
        for(; j+3<cnt; j+=4){
            int d0 = g_edst[base+j]   & NMASK;
            int d1 = g_edst[base+j+1] & NMASK;
            int d2 = g_edst[base+j+2] & NMASK;
            int d3 = g_edst[base+j+3] & NMASK;
            float4 p0 = ((const float4*)(g_s1 + d0*K1P))[lane];
            float4 p1 = ((const float4*)(g_s1 + d1*K1P))[lane];
            float4 p2 = ((const float4*)(g_s1 + d2*K1P))[lane];
            float4 p3 = ((const float4*)(g_s1 + d3*K1P))[lane];
            float t0 = a.x*p0.x + a.y*p0.y + a.z*p0.z + a.w*p0.w;
            float t1 = a.x*p1.x + a.y*p1.y + a.z*p1.z + a.w*p1.w;
            float t2 = a.x*p2.x + a.y*p2.y + a.z*p2.z + a.w*p2.w;
            float t3 = a.x*p3.x + a.y*p3.y + a.z*p3.z + a.w*p3.w;
            #pragma unroll
            for(int o=16;o;o>>=1){
                t0 += __shfl_xor_sync(FULL,t0,o);
                t1 += __shfl_xor_sync(FULL,t1,o);
                t2 += __shfl_xor_sync(FULL,t2,o);
                t3 += __shfl_xor_sync(FULL,t3,o);
            }
            float q0 = fmaxf(sqn + g_sq1[d0] - 2.f*t0, 0.f);
            float q1 = fmaxf(sqn + g_sq1[d1] - 2.f*t1, 0.f);
            float q2 = fmaxf(sqn + g_sq1[d2] - 2.f*t2, 0.f);
            float q3 = fmaxf(sqn + g_sq1[d3] - 2.f*t3, 0.f);
            float s0 = (q0>0.f)? sqrtf(q0) : 0.f;
            float s1v = (q1>0.f)? sqrtf(q1) : 0.f;
            float s2v = (q2>0.f)? sqrtf(q2) : 0.f;
            float s3 = (q3>0.f)? sqrtf(q3) : 0.f;
            if(lane==0){
                g_dist[base+j]   = s0;
                g_dist[base+j+1] = s1v;
                g_dist[base+j+2] = s2v;
                g_dist[base+j+3] = s3;
                rsum += (s0+s1v)+(s2v+s3);
                dsum += (t0+t1)+(t2+t3);
            }
        }
        for(; j<cnt; j++){
            int d0 = g_edst[base+j] & NMASK;
            float4 p0 = ((const float4*)(g_s1 + d0*K1P))[lane];
            float t0 = a.x*p0.x + a.y*p0.y + a.z*p0.z + a.w*p0.w;
            #pragma unroll
            for(int o=16;o;o>>=1) t0 += __shfl_xor_sync(FULL,t0,o);
            float q0 = fmaxf(sqn + g_sq1[d0] - 2.f*t0, 0.f);
            float s0 = (q0>0.f)? sqrtf(q0) : 0.f;
            if(lane==0){ g_dist[base+j]=s0; rsum+=s0; dsum+=t0; }
        }
        if(lane==0){
            g_invd[n] = 1.f/(sqrtf(rsum) + EPSL);
            atomicAdd(&sas_sh, dsum);
            atomicAdd(&sds_sh, (float)cnt*sqn);
            atomicAdd(&tr1_sh, sqn);
        }
    }
    __syncthreads();
    if(threadIdx.x==0){
        int b = (blockIdx.x>>7) & (NB-1);
        atomicAdd(&g_sas[b], sas_sh);
        atomicAdd(&g_sds[b], sds_sh);
        atomicAdd(&g_tr1[b], tr1_sh);
    }
}

// ---------------- tf32 tensor-core gram (8 warps, full-K, no materialization) ----------------
__device__ __forceinline__ unsigned cvt_tf32(float v){
    unsigned r;
    asm("cvt.rna.tf32.f32 %0, %1;" : "=r"(r) : "f"(v));
    return r;
}
__device__ __forceinline__ void mma_tf32(float* c, const unsigned* a, const unsigned* b){
    asm("mma.sync.aligned.m16n8k8.row.col.f32.tf32.tf32.f32 "
        "{%0,%1,%2,%3}, {%4,%5,%6,%7}, {%8,%9}, {%0,%1,%2,%3};"
        : "+f"(c[0]),"+f"(c[1]),"+f"(c[2]),"+f"(c[3])
        : "r"(a[0]),"r"(a[1]),"r"(a[2]),"r"(a[3]), "r"(b[0]),"r"(b[1]));
}
#define GT_STR 132

__global__ void gram_tc3_kernel(){
    int b  = blockIdx.x >> 3;        // batch
    int cg = blockIdx.x & 7;         // column group: 16 cols of C
    __shared__ float sh[32*GT_STR];
    int tid = threadIdx.x;           // 256 threads = 8 warps
    int w = tid>>5, lane = tid&31;
    int g = lane>>2, t = lane&3;
    int R = w*16;                    // warp rows: 16 each, 8 warps = 128
    int C = cg*16;
    float acc[2][4];
    #pragma unroll
    for(int i=0;i<2;i++){
        #pragma unroll
        for(int j=0;j<4;j++) acc[i][j]=0.f;
    }
    for(int chunk=0; chunk<32; chunk++){
        int nbase = b*NN + chunk*32;
        __syncthreads();
        for(int i=tid;i<32*32;i+=256){
            int nn = i>>5, cc = (i&31)<<2;
            float4 v = *(const float4*)(g_s1 + (nbase+nn)*K1P + cc);
            float* d = sh + nn*GT_STR + cc;
            d[0]=v.x; d[1]=v.y; d[2]=v.z; d[3]=v.w;
        }
        __syncthreads();
        #pragma unroll
        for(int ks=0;ks<4;ks++){
            int n0 = ks*8;
            unsigned af[4];
            af[0] = cvt_tf32(sh[(n0+t  )*GT_STR + R+g  ]);
            af[1] = cvt_tf32(sh[(n0+t  )*GT_STR + R+g+8]);
            af[2] = cvt_tf32(sh[(n0+t+4)*GT_STR + R+g  ]);
            af[3] = cvt_tf32(sh[(n0+t+4)*GT_STR + R+g+8]);
            #pragma unroll
            for(int ct=0;ct<2;ct++){
                unsigned bf[2];
                int col = C + ct*8 + g;
                bf[0] = cvt_tf32(sh[(n0+t  )*GT_STR + col]);
                bf[1] = cvt_tf32(sh[(n0+t+4)*GT_STR + col]);
                mma_tf32(acc[ct], af, bf);
            }
        }
    }
    // sum of squares (pad rows/cols are exactly 0)
    float ss = 0.f;
    #pragma unroll
    for(int i=0;i<2;i++){
        #pragma unroll
        for(int j=0;j<4;j++) ss += acc[i][j]*acc[i][j];
    }
    #pragma unroll
    for(int o=16;o;o>>=1) ss += __shfl_xor_sync(FULL,ss,o);
    if(lane==0) atomicAdd(&g_fro2[b], ss);
}

// ---------------- fused edge pass 2 + node pass 2 ; caches w into g_dist ----------------
__global__ void mid_kernel(const float* __restrict__ relw, const float* __restrict__ relb,
                           const float* __restrict__ rtw, const float* __restrict__ pw,
                           const float* __restrict__ pb){
    __shared__ float ss2sh[K2*K2];
    __shared__ float den_sh, tr2_sh;
    for(int i=threadIdx.x;i<K2*K2;i+=blockDim.x) ss2sh[i]=0.f;
    if(threadIdx.x==0){ den_sh=0.f; tr2_sh=0.f; }
    __syncthreads();
    int n    = (blockIdx.x*blockDim.x + threadIdx.x)>>5;
    int lane = threadIdx.x & 31;
    int lk   = lane & 15;
    if(n<NTOT){
        float invn = g_invd[n];
        int cnt = g_cnt[n]; if(cnt>DMAX) cnt=DMAX; if(cnt<0) cnt=0;
        int base = n*DMAX;
        float z=0.f, rw=0.f;
        int j=0;
        for(; j+1<cnt; j+=2){
            int d0 = g_edst[base+j]   & NMASK;
            int d1 = g_edst[base+j+1] & NMASK;
            float w0 = g_dist[base+j]  *invn*g_invd[d0];
            float w1 = g_dist[base+j+1]*invn*g_invd[d1];
            z  += w0*g_h1[d0*HID+lane] + w1*g_h1[d1*HID+lane];
            rw += w0+w1;
            if(lane==0){ g_dist[base+j]=w0; g_dist[base+j+1]=w1; }
        }
        if(j<cnt){
            int d0 = g_edst[base+j] & NMASK;
            float w0 = g_dist[base+j]*invn*g_invd[d0];
            z  += w0*g_h1[d0*HID+lane];
            rw += w0;
            if(lane==0) g_dist[base+j]=w0;
        }
        float h1v = g_h1[n*HID+lane];
        float h = relb[lane];
        #pragma unroll
        for(int c=0;c<32;c++){
            h += __shfl_sync(FULL,z,c)*relw[c*HID+lane] + __shfl_sync(FULL,h1v,c)*rtw[c*HID+lane];
        }
        g_h2[n*HID+lane] = h;
        float pbv = pb[lk];
        float l = (lane<K2)? pbv : -1e30f;
        #pragma unroll
        for(int c=0;c<32;c++){
            float hv = __shfl_sync(FULL,h,c);
            l += hv*pw[c*K2+lk];
        }
        float m = l;
        for(int o=16;o;o>>=1) m = fmaxf(m, __shfl_xor_sync(FULL,m,o));
        float ev = (lane<K2)? expf(l-m) : 0.f;
        float s = ev;
        for(int o=16;o;o>>=1) s += __shfl_xor_sync(FULL,s,o);
        float sv = ev/s;
        if(lane<K2) g_s2[n*K2+lane] = sv;
        float sq = sv*sv;
        for(int o=16;o;o>>=1) sq += __shfl_xor_sync(FULL,sq,o);
        #pragma unroll
        for(int p=0;p<8;p++){
            int idx = lane*8+p; int k = idx>>4, lc = idx&15;
            float v = __shfl_sync(FULL,sv,k)*__shfl_sync(FULL,sv,lc);
            atomicAdd(&ss2sh[idx], v);
        }
        if(lane==0){
            atomicAdd(&den_sh, rw*sq);
            atomicAdd(&tr2_sh, sq);
        }
    }
    __syncthreads();
    int b = (blockIdx.x>>7) & (NB-1);
    if(threadIdx.x<K2*K2) atomicAdd(&g_SS2[b*K2*K2+threadIdx.x], ss2sh[threadIdx.x]);
    if(threadIdx.x==0){ atomicAdd(&g_den[b], den_sh); atomicAdd(&g_tr2[b], tr2_sh); }
}

// ---------------- edge pass 3: Y = Σ w * s2[d]  (w precomputed by mid) ----------------
__global__ void edge3_kernel(){
    int gw   = (blockIdx.x*blockDim.x + threadIdx.x)>>5;
    int lane = threadIdx.x & 31;
    int lk   = lane & 15;
    int n    = gw*2 + (lane>>4);
    if(n>=NTOT) return;
    int cnt = g_cnt[n]; if(cnt>DMAX) cnt=DMAX; if(cnt<0) cnt=0;
    int base = n*DMAX;
    float y=0.f;
    int j=0;
    for(; j+1<cnt; j+=2){
        int d0 = g_edst[base+j]   & NMASK;
        int d1 = g_edst[base+j+1] & NMASK;
        float w0 = g_dist[base+j];
        float w1 = g_dist[base+j+1];
        y += w0*g_s2[d0*K2+lk] + w1*g_s2[d1*K2+lk];
    }
    if(j<cnt){
        int d0 = g_edst[base+j] & NMASK;
        y += g_dist[base+j]*g_s2[d0*K2+lk];
    }
    g_Y[n*K2+lk] = y;
}

// ---------------- pooled out = S2^T h2 ; out_adj = S2^T Y ----------------
__global__ void pool_kernel(){
    int b = blockIdx.x & (NB-1), ch = blockIdx.y & 7;
    __shared__ float s2t[16*K2], h2t[16*HID], yt[16*K2];
    int tid = threadIdx.x;
    int ko = tid>>5, c = tid&31, ka = tid>>4, la = tid&15;
    float a0=0.f, a1=0.f, a2=0.f;
    for(int t=0;t<8;t++){
        int nb = b*NN + ch*128 + t*16;
        for(int i=tid;i<16*K2;i+=256){ s2t[i]=g_s2[nb*K2+i]; yt[i]=g_Y[nb*K2+i]; }
        for(int i=tid;i<16*HID;i+=256) h2t[i]=g_h2[nb*HID+i];
        __syncthreads();
        #pragma unroll
        for(int nn=0;nn<16;nn++){
            float hv = h2t[nn*HID+c];
            a0 += s2t[nn*K2+ko]*hv;
            a1 += s2t[nn*K2+ko+8]*hv;
            a2 += s2t[nn*K2+ka]*yt[nn*K2+la];
        }
        __syncthreads();
    }
    atomicAdd(&g_outp[b*K2*HID + tid], a0);
    atomicAdd(&g_outp[b*K2*HID + 256 + tid], a1);
    atomicAdd(&g_outadj[b*K2*K2 + tid], a2);
}

// ---------------- final: mincut norm, conv2, MLP head, losses + self-clean ----------------
__global__ void final_kernel(const float* __restrict__ r2w, const float* __restrict__ r2b,
                             const float* __restrict__ rt2w, const float* __restrict__ l2w,
                             const float* __restrict__ l2b, const float* __restrict__ l3w,
                             const float* __restrict__ l3b, float* __restrict__ out,
                             int out_size){
    __shared__ float A[NB][K2*K2];
    __shared__ float loss1[NB], loss2[NB];
    int wid  = threadIdx.x>>5;
    int lane = threadIdx.x & 31;
    int lr   = lane & 15;
    int b = wid;
    for(int i=lane;i<K2*K2;i+=32) A[b][i] = g_outadj[b*K2*K2+i];
    __syncwarp();
    float diagv = A[b][lr*17];
    float trv = (lane<K2)? diagv : 0.f;
    for(int o=16;o;o>>=1) trv += __shfl_xor_sync(FULL,trv,o);
    if(lane<K2) A[b][lr*17] = 0.f;
    __syncwarp();
    float rsum=0.f;
    for(int l=0;l<K2;l++) rsum += A[b][lr*K2+l];
    float di = 1.f/(sqrtf(fmaxf(rsum,0.f))+EPSL);
    float dinv = (lane<K2)? di : 0.f;
    float cs = 0.f;
    for(int k=0;k<K2;k++){
        float dk = __shfl_sync(FULL,dinv,k);
        cs += A[b][k*K2+lr]*dk;
    }
    cs *= dinv;
    float ov[16];
    #pragma unroll
    for(int l=0;l<16;l++) ov[l] = g_outp[b*K2*HID + l*HID + lane];
    float u1=0.f, osum=0.f;
    #pragma unroll
    for(int l=0;l<16;l++){
        u1   += __shfl_sync(FULL,cs,l)*ov[l];
        osum += ov[l];
    }
    float v = 16.f*r2b[lane];
    #pragma unroll
    for(int c=0;c<32;c++){
        v += __shfl_sync(FULL,u1,c)*r2w[c*HID+lane] + __shfl_sync(FULL,osum,c)*rt2w[c*HID+lane];
    }
    float r = l2b[lane];
    #pragma unroll
    for(int c=0;c<32;c++) r += __shfl_sync(FULL,v,c)*l2w[c*HID+lane];
    r = fmaxf(r, 0.f);
    int lc10 = (lane<COUT)? lane : 0;
    float l3bv = l3b[lc10];
    float lg = (lane<COUT)? l3bv : -1e30f;
    #pragma unroll
    for(int c=0;c<32;c++){
        float rv = __shfl_sync(FULL,r,c);
        lg += rv*l3w[c*COUT+lc10];
    }
    float m = lg;
    for(int o=16;o;o>>=1) m = fmaxf(m, __shfl_xor_sync(FULL,m,o));
    float ez = (lane<COUT)? expf(lg-m) : 0.f;
    float se = ez;
    for(int o=16;o;o>>=1) se += __shfl_xor_sync(FULL,se,o);
    if(lane<COUT && (b*COUT+lane)<out_size) out[b*COUT+lane] = lg - m - logf(se);
    float f = 0.f;
    for(int i=lane;i<K2*K2;i+=32){ float vv=g_SS2[b*K2*K2+i]; f += vv*vv; }
    for(int o=16;o;o>>=1) f += __shfl_xor_sync(FULL,f,o);
    if(lane==0){
        float fro2 = sqrtf(f);
        float fro1 = sqrtf(g_fro2[b]);
        float term1 = (g_sds[b]-g_sas[b])/(g_sds[b]+EPSL);
        float o1b = sqrtf(fmaxf(2.f - 2.f*g_tr1[b]/(fro1*10.f), 0.f));
        float mcb = -(trv/(g_den[b]+EPSL));
        float o2b = sqrtf(fmaxf(2.f - 2.f*g_tr2[b]/(fro2*4.f), 0.f));
        loss1[b] = term1 + o1b;
        loss2[b] = mcb + o2b;
    }
    __syncthreads();
    if(threadIdx.x==0){
        float s1v=0.f, s2v=0.f;
        for(int i=0;i<NB;i++){ s1v+=loss1[i]; s2v+=loss2[i]; }
        if(out_size > NB*COUT)   out[NB*COUT]   = s1v/NB;
        if(out_size > NB*COUT+1) out[NB*COUT+1] = s2v/NB;
    }
    // ---- self-clean: restore zero-state for the next graph replay ----
    __syncthreads();
    int tid = threadIdx.x;
    for(int i=tid; i<NTOT; i+=512) g_cnt[i] = 0;
    for(int i=tid; i<NB*K2*HID; i+=512) g_outp[i] = 0.f;
    for(int i=tid; i<NB*K2*K2; i+=512){ g_SS2[i]=0.f; g_outadj[i]=0.f; }
    if(tid<NB){
        g_sas[tid]=0.f; g_sds[tid]=0.f; g_tr1[tid]=0.f;
        g_tr2[tid]=0.f; g_den[tid]=0.f; g_fro2[tid]=0.f;
    }
}

// ---------------- launcher: chain A enqueued first; tiny gram chain on s2 ----------------
extern "C" void kernel_launch(void* const* d_in, const int* in_sizes, int n_in,
                              void* d_out, int out_size){
    const float* x    = (const float*)d_in[0];
    const float* l1w  = (const float*)d_in[1];
    const float* l1b  = (const float*)d_in[2];
    const float* p1w  = (const float*)d_in[3];
    const float* p1b  = (const float*)d_in[4];
    const float* p2w  = (const float*)d_in[5];
    const float* p2b  = (const float*)d_in[6];
    const float* c1rw = (const float*)d_in[7];
    const float* c1rb = (const float*)d_in[8];
    const float* c1rt = (const float*)d_in[9];
    const float* c2rw = (const float*)d_in[10];
    const float* c2rb = (const float*)d_in[11];
    const float* c2rt = (const float*)d_in[12];
    const float* l2w  = (const float*)d_in[13];
    const float* l2b  = (const float*)d_in[14];
    const float* l3w  = (const float*)d_in[15];
    const float* l3b  = (const float*)d_in[16];
    const int*   ei   = (const int*)d_in[17];
    const int* src = ei;
    const int* dst = ei + NE;
    float* out = (float*)d_out;

    static cudaStream_t s2 = 0;
    static cudaEvent_t evFork = 0, evJoin = 0;
    if(!s2){
        cudaStreamCreateWithFlags(&s2, cudaStreamNonBlocking);
        cudaEventCreateWithFlags(&evFork, cudaEventDisableTiming);
        cudaEventCreateWithFlags(&evJoin, cudaEventDisableTiming);
    }

    front_kernel<<<1024+2048,256>>>(src, dst, x, l1w, l1b, p1w, p1b);
    cudaEventRecord(evFork, 0);              // fork point: after front only

    // chain A enqueued first -> scheduler priority for the critical path
    edge1_kernel<<<NTOT/8,256>>>();
    mid_kernel<<<NTOT/8,256>>>(c1rw, c1rb, c1rt, p2w, p2b);
    edge3_kernel<<<NTOT/16,256>>>();
    pool_kernel<<<dim3(NB,8),256>>>();

    // chain B on s2: single small tensor-core gram kernel
    cudaStreamWaitEvent(s2, evFork, 0);
    gram_tc3_kernel<<<NB*8,256,0,s2>>>();
    cudaEventRecord(evJoin, s2);

    // join: final needs g_fro2 from the gram chain
    cudaStreamWaitEvent(0, evJoin, 0);
    final_kernel<<<1,512>>>(c2rw, c2rb, c2rt, l2w, l2b, l3w, l3b, out, out_size);
}

// round 17
// speedup vs baseline: 1.5244x; 1.5244x over previous
#include <cuda_runtime.h>
#include <math.h>

#define NB 16
#define NN 1024
#define NTOT 16384
#define NMASK 16383
#define NE 262144
#define CIN 64
#define HID 32
#define K1 100
#define K1P 128
#define K2 16
#define COUT 10
#define DMAX 64
#define EPSL 1e-15f
#define FULL 0xffffffffu
#define GP_KS 8          // gram K-slices per batch

// ---------------- scratch (device globals; zero-initialized at load; self-cleaned) ----------------
__device__ float g_h1[NTOT*HID];
__device__ float g_s1[NTOT*K1P];     // 128-stride rows, tail zeroed
__device__ float g_sq1[NTOT];
__device__ float g_dist[NTOT*DMAX];  // edge1: dist ; after mid: final weight w
__device__ float g_invd[NTOT];
__device__ float g_h2[NTOT*HID];
__device__ float g_s2[NTOT*K2];
__device__ float g_Y[NTOT*K2];
__device__ float g_gpart[GP_KS*NB*K1P*K1P];   // 8 MB split-K gram partials
__device__ float g_fro2[NB];         // sum-of-squares of S1^T S1 per batch
__device__ float g_SS2[NB*K2*K2];
__device__ float g_outp[NB*K2*HID];
__device__ float g_outadj[NB*K2*K2];
__device__ float g_sas[NB], g_sds[NB], g_tr1[NB], g_tr2[NB], g_den[NB];
__device__ int   g_cnt[NTOT];
__device__ int   g_edst[NTOT*DMAX];

// ---------------- fused: edge bucketing (blocks 0..1023) + node pass 1 ----------------
__global__ void front_kernel(const int* __restrict__ src, const int* __restrict__ dst,
                             const float* __restrict__ x, const float* __restrict__ w1,
                             const float* __restrict__ b1, const float* __restrict__ pw,
                             const float* __restrict__ pb){
    if(blockIdx.x < 1024){
        int e = blockIdx.x*256 + threadIdx.x;
        int s = src[e] & NMASK;
        int slot = atomicAdd(&g_cnt[s], 1);
        if(slot < DMAX) g_edst[s*DMAX + slot] = dst[e] & NMASK;
        return;
    }
    int n    = ((blockIdx.x-1024)*256 + threadIdx.x)>>5;
    int lane = threadIdx.x & 31;
    if(n>=NTOT) return;
    int l3i = lane & 3;
    float x0 = x[n*CIN+lane], x1 = x[n*CIN+32+lane];
    float h = b1[lane];
    #pragma unroll
    for(int c=0;c<32;c++) h += __shfl_sync(FULL,x0,c)*w1[c*HID+lane];
    #pragma unroll
    for(int c=0;c<32;c++) h += __shfl_sync(FULL,x1,c)*w1[(32+c)*HID+lane];
    g_h1[n*HID+lane] = h;
    float l0=pb[lane], l1=pb[lane+32], l2=pb[lane+64];
    float pb3 = pb[96+l3i];
    float l3 = (lane<4)? pb3 : -1e30f;
    #pragma unroll
    for(int c=0;c<32;c++){
        float hv = __shfl_sync(FULL,h,c);
        l0 += hv*pw[c*K1+lane];
        l1 += hv*pw[c*K1+lane+32];
        l2 += hv*pw[c*K1+lane+64];
        l3 += hv*pw[c*K1+96+l3i];
    }
    float m = fmaxf(fmaxf(l0,l1),fmaxf(l2,l3));
    for(int o=16;o;o>>=1) m = fmaxf(m, __shfl_xor_sync(FULL,m,o));
    float e0=expf(l0-m), e1=expf(l1-m), e2=expf(l2-m);
    float e3 = (lane<4)? expf(l3-m) : 0.f;
    float s = e0+e1+e2+e3;
    for(int o=16;o;o>>=1) s += __shfl_xor_sync(FULL,s,o);
    float inv = 1.f/s;
    e0*=inv; e1*=inv; e2*=inv; e3*=inv;
    g_s1[n*K1P+lane]=e0; g_s1[n*K1P+lane+32]=e1; g_s1[n*K1P+lane+64]=e2;
    g_s1[n*K1P+96+lane] = (lane<4)? e3 : 0.f;
    float sq = e0*e0+e1*e1+e2*e2+e3*e3;
    for(int o=16;o;o>>=1) sq += __shfl_xor_sync(FULL,sq,o);
    if(lane==0) g_sq1[n]=sq;
}

// ---------------- edge pass 1: 4-edge-unrolled dist+dot; invd inline; sas/sds/tr1 ----------------
__global__ void edge1_kernel(){
    __shared__ float sas_sh, sds_sh, tr1_sh;
    if(threadIdx.x==0){ sas_sh=0.f; sds_sh=0.f; tr1_sh=0.f; }
    __syncthreads();
    int n    = (blockIdx.x*blockDim.x + threadIdx.x)>>5;
    int lane = threadIdx.x & 31;
    if(n<NTOT){
        float4 a = ((const float4*)(g_s1 + n*K1P))[lane];
        float sqn = g_sq1[n];
        int cnt = g_cnt[n]; if(cnt>DMAX) cnt=DMAX; if(cnt<0) cnt=0;
        int base = n*DMAX;
        float rsum=0.f, dsum=0.f;
        int j=0;
        for(; j+3<cnt; j+=4){
            int d0 = g_edst[base+j]   & NMASK;
            int d1 = g_edst[base+j+1] & NMASK;
            int d2 = g_edst[base+j+2] & NMASK;
            int d3 = g_edst[base+j+3] & NMASK;
            float4 p0 = ((const float4*)(g_s1 + d0*K1P))[lane];
            float4 p1 = ((const float4*)(g_s1 + d1*K1P))[lane];
            float4 p2 = ((const float4*)(g_s1 + d2*K1P))[lane];
            float4 p3 = ((const float4*)(g_s1 + d3*K1P))[lane];
            float t0 = a.x*p0.x + a.y*p0.y + a.z*p0.z + a.w*p0.w;
            float t1 = a.x*p1.x + a.y*p1.y + a.z*p1.z + a.w*p1.w;
            float t2 = a.x*p2.x + a.y*p2.y + a.z*p2.z + a.w*p2.w;
            float t3 = a.x*p3.x + a.y*p3.y + a.z*p3.z + a.w*p3.w;
            #pragma unroll
            for(int o=16;o;o>>=1){
                t0 += __shfl_xor_sync(FULL,t0,o);
                t1 += __shfl_xor_sync(FULL,t1,o);
                t2 += __shfl_xor_sync(FULL,t2,o);
                t3 += __shfl_xor_sync(FULL,t3,o);
            }
            float q0 = fmaxf(sqn + g_sq1[d0] - 2.f*t0, 0.f);
            float q1 = fmaxf(sqn + g_sq1[d1] - 2.f*t1, 0.f);
            float q2 = fmaxf(sqn + g_sq1[d2] - 2.f*t2, 0.f);
            float q3 = fmaxf(sqn + g_sq1[d3] - 2.f*t3, 0.f);
            float s0 = (q0>0.f)? sqrtf(q0) : 0.f;
            float s1v = (q1>0.f)? sqrtf(q1) : 0.f;
            float s2v = (q2>0.f)? sqrtf(q2) : 0.f;
            float s3 = (q3>0.f)? sqrtf(q3) : 0.f;
            if(lane==0){
                g_dist[base+j]   = s0;
                g_dist[base+j+1] = s1v;
                g_dist[base+j+2] = s2v;
                g_dist[base+j+3] = s3;
                rsum += (s0+s1v)+(s2v+s3);
                dsum += (t0+t1)+(t2+t3);
            }
        }
        for(; j<cnt; j++){
            int d0 = g_edst[base+j] & NMASK;
            float4 p0 = ((const float4*)(g_s1 + d0*K1P))[lane];
            float t0 = a.x*p0.x + a.y*p0.y + a.z*p0.z + a.w*p0.w;
            #pragma unroll
            for(int o=16;o;o>>=1) t0 += __shfl_xor_sync(FULL,t0,o);
            float q0 = fmaxf(sqn + g_sq1[d0] - 2.f*t0, 0.f);
            float s0 = (q0>0.f)? sqrtf(q0) : 0.f;
            if(lane==0){ g_dist[base+j]=s0; rsum+=s0; dsum+=t0; }
        }
        if(lane==0){
            g_invd[n] = 1.f/(sqrtf(rsum) + EPSL);
            atomicAdd(&sas_sh, dsum);
            atomicAdd(&sds_sh, (float)cnt*sqn);
            atomicAdd(&tr1_sh, sqn);
        }
    }
    __syncthreads();
    if(threadIdx.x==0){
        int b = (blockIdx.x>>7) & (NB-1);
        atomicAdd(&g_sas[b], sas_sh);
        atomicAdd(&g_sds[b], sds_sh);
        atomicAdd(&g_tr1[b], tr1_sh);
    }
}

// ---------------- split-K fp32 gram: partial G = S_slice^T S_slice ----------------
#define GSTR 132   // 32-node chunk row stride (128 + 4 pad)

__global__ void gram2_kernel(){
    int blk = blockIdx.x;
    int b  = blk >> 3;          // batch
    int ks = blk & 7;           // K-slice (128 nodes)
    __shared__ float sh[32*GSTR];
    int tid = threadIdx.x;
    int tx = tid & 15, ty = tid >> 4;   // 16x16 thread grid
    float acc[8][8];
    #pragma unroll
    for(int i=0;i<8;i++)
        #pragma unroll
        for(int j=0;j<8;j++) acc[i][j]=0.f;
    for(int sc=0; sc<4; sc++){
        int nbase = b*NN + ks*128 + sc*32;
        __syncthreads();
        for(int i=tid;i<32*32;i+=256){
            int nn = i>>5, cc = (i&31)<<2;
            float4 v = *(const float4*)(g_s1 + (nbase+nn)*K1P + cc);
            *(float4*)(sh + nn*GSTR + cc) = v;
        }
        __syncthreads();
        #pragma unroll 4
        for(int nn=0; nn<32; nn++){
            const float* row = sh + nn*GSTR;
            float4 a0 = *(const float4*)(row + ty*8);
            float4 a1 = *(const float4*)(row + ty*8 + 4);
            float4 b0 = *(const float4*)(row + tx*4);
            float4 b1 = *(const float4*)(row + 64 + tx*4);
            float av[8] = {a0.x,a0.y,a0.z,a0.w,a1.x,a1.y,a1.z,a1.w};
            float bv[8] = {b0.x,b0.y,b0.z,b0.w,b1.x,b1.y,b1.z,b1.w};
            #pragma unroll
            for(int i=0;i<8;i++)
                #pragma unroll
                for(int j=0;j<8;j++) acc[i][j] += av[i]*bv[j];
        }
    }
    float* dst = g_gpart + (ks*NB + b)*K1P*K1P;
    #pragma unroll
    for(int i=0;i<8;i++){
        int r = ty*8+i;
        float4 o0 = make_float4(acc[i][0],acc[i][1],acc[i][2],acc[i][3]);
        float4 o1 = make_float4(acc[i][4],acc[i][5],acc[i][6],acc[i][7]);
        *(float4*)(dst + r*K1P + tx*4)      = o0;
        *(float4*)(dst + r*K1P + 64 + tx*4) = o1;
    }
}

// ---------------- reduce split-K partials -> ||G||_F^2 per batch ----------------
__global__ void fro_reduce_kernel(){
    int idx = blockIdx.x*256 + threadIdx.x;      // 0..65535
    int b = idx >> 12;                           // 4096 float4-entries per batch
    float4 v = make_float4(0.f,0.f,0.f,0.f);
    #pragma unroll
    for(int ks=0; ks<GP_KS; ks++){
        float4 p = *(const float4*)(g_gpart + ks*NB*K1P*K1P + idx*4);
        v.x += p.x; v.y += p.y; v.z += p.z; v.w += p.w;
    }
    float ss = v.x*v.x + v.y*v.y + v.z*v.z + v.w*v.w;
    #pragma unroll
    for(int o=16;o;o>>=1) ss += __shfl_xor_sync(FULL,ss,o);
    if((threadIdx.x&31)==0) atomicAdd(&g_fro2[b], ss);
}

// ---------------- fused edge pass 2 + node pass 2 ; caches w into g_dist ----------------
__global__ void mid_kernel(const float* __restrict__ relw, const float* __restrict__ relb,
                           const float* __restrict__ rtw, const float* __restrict__ pw,
                           const float* __restrict__ pb){
    __shared__ float ss2sh[K2*K2];
    __shared__ float den_sh, tr2_sh;
    for(int i=threadIdx.x;i<K2*K2;i+=blockDim.x) ss2sh[i]=0.f;
    if(threadIdx.x==0){ den_sh=0.f; tr2_sh=0.f; }
    __syncthreads();
    int n    = (blockIdx.x*blockDim.x + threadIdx.x)>>5;
    int lane = threadIdx.x & 31;
    int lk   = lane & 15;
    if(n<NTOT){
        float invn = g_invd[n];
        int cnt = g_cnt[n]; if(cnt>DMAX) cnt=DMAX; if(cnt<0) cnt=0;
        int base = n*DMAX;
        float z=0.f, rw=0.f;
        int j=0;
        for(; j+1<cnt; j+=2){
            int d0 = g_edst[base+j]   & NMASK;
            int d1 = g_edst[base+j+1] & NMASK;
            float w0 = g_dist[base+j]  *invn*g_invd[d0];
            float w1 = g_dist[base+j+1]*invn*g_invd[d1];
            z  += w0*g_h1[d0*HID+lane] + w1*g_h1[d1*HID+lane];
            rw += w0+w1;
            if(lane==0){ g_dist[base+j]=w0; g_dist[base+j+1]=w1; }
        }
        if(j<cnt){
            int d0 = g_edst[base+j] & NMASK;
            float w0 = g_dist[base+j]*invn*g_invd[d0];
            z  += w0*g_h1[d0*HID+lane];
            rw += w0;
            if(lane==0) g_dist[base+j]=w0;
        }
        float h1v = g_h1[n*HID+lane];
        float h = relb[lane];
        #pragma unroll
        for(int c=0;c<32;c++){
            h += __shfl_sync(FULL,z,c)*relw[c*HID+lane] + __shfl_sync(FULL,h1v,c)*rtw[c*HID+lane];
        }
        g_h2[n*HID+lane] = h;
        float pbv = pb[lk];
        float l = (lane<K2)? pbv : -1e30f;
        #pragma unroll
        for(int c=0;c<32;c++){
            float hv = __shfl_sync(FULL,h,c);
            l += hv*pw[c*K2+lk];
        }
        float m = l;
        for(int o=16;o;o>>=1) m = fmaxf(m, __shfl_xor_sync(FULL,m,o));
        float ev = (lane<K2)? expf(l-m) : 0.f;
        float s = ev;
        for(int o=16;o;o>>=1) s += __shfl_xor_sync(FULL,s,o);
        float sv = ev/s;
        if(lane<K2) g_s2[n*K2+lane] = sv;
        float sq = sv*sv;
        for(int o=16;o;o>>=1) sq += __shfl_xor_sync(FULL,sq,o);
        #pragma unroll
        for(int p=0;p<8;p++){
            int idx = lane*8+p; int k = idx>>4, lc = idx&15;
            float v = __shfl_sync(FULL,sv,k)*__shfl_sync(FULL,sv,lc);
            atomicAdd(&ss2sh[idx], v);
        }
        if(lane==0){
            atomicAdd(&den_sh, rw*sq);
            atomicAdd(&tr2_sh, sq);
        }
    }
    __syncthreads();
    int b = (blockIdx.x>>7) & (NB-1);
    if(threadIdx.x<K2*K2) atomicAdd(&g_SS2[b*K2*K2+threadIdx.x], ss2sh[threadIdx.x]);
    if(threadIdx.x==0){ atomicAdd(&g_den[b], den_sh); atomicAdd(&g_tr2[b], tr2_sh); }
}

// ---------------- edge pass 3: Y = Σ w * s2[d]; zeroes g_cnt (last reader) ----------------
__global__ void edge3_kernel(){
    int gw   = (blockIdx.x*blockDim.x + threadIdx.x)>>5;
    int lane = threadIdx.x & 31;
    int lk   = lane & 15;
    int n    = gw*2 + (lane>>4);
    if(n>=NTOT) return;
    int cnt = g_cnt[n]; if(cnt>DMAX) cnt=DMAX; if(cnt<0) cnt=0;
    int base = n*DMAX;
    float y=0.f;
    int j=0;
    for(; j+1<cnt; j+=2){
        int d0 = g_edst[base+j]   & NMASK;
        int d1 = g_edst[base+j+1] & NMASK;
        float w0 = g_dist[base+j];
        float w1 = g_dist[base+j+1];
        y += w0*g_s2[d0*K2+lk] + w1*g_s2[d1*K2+lk];
    }
    if(j<cnt){
        int d0 = g_edst[base+j] & NMASK;
        y += g_dist[base+j]*g_s2[d0*K2+lk];
    }
    g_Y[n*K2+lk] = y;
    if(lk==0) g_cnt[n] = 0;      // distributed self-clean (edge3 is last reader)
}

// ---------------- pooled out = S2^T h2 ; out_adj = S2^T Y ----------------
__global__ void pool_kernel(){
    int b = blockIdx.x & (NB-1), ch = blockIdx.y & 7;
    __shared__ float s2t[16*K2], h2t[16*HID], yt[16*K2];
    int tid = threadIdx.x;
    int ko = tid>>5, c = tid&31, ka = tid>>4, la = tid&15;
    float a0=0.f, a1=0.f, a2=0.f;
    for(int t=0;t<8;t++){
        int nb = b*NN + ch*128 + t*16;
        for(int i=tid;i<16*K2;i+=256){ s2t[i]=g_s2[nb*K2+i]; yt[i]=g_Y[nb*K2+i]; }
        for(int i=tid;i<16*HID;i+=256) h2t[i]=g_h2[nb*HID+i];
        __syncthreads();
        #pragma unroll
        for(int nn=0;nn<16;nn++){
            float hv = h2t[nn*HID+c];
            a0 += s2t[nn*K2+ko]*hv;
            a1 += s2t[nn*K2+ko+8]*hv;
            a2 += s2t[nn*K2+ka]*yt[nn*K2+la];
        }
        __syncthreads();
    }
    atomicAdd(&g_outp[b*K2*HID + tid], a0);
    atomicAdd(&g_outp[b*K2*HID + 256 + tid], a1);
    atomicAdd(&g_outadj[b*K2*K2 + tid], a2);
}

// ---------------- final: mincut norm, conv2, MLP head, losses + self-clean ----------------
__global__ void final_kernel(const float* __restrict__ r2w, const float* __restrict__ r2b,
                             const float* __restrict__ rt2w, const float* __restrict__ l2w,
                             const float* __restrict__ l2b, const float* __restrict__ l3w,
                             const float* __restrict__ l3b, float* __restrict__ out,
                             int out_size){
    __shared__ float A[NB][K2*K2];
    __shared__ float loss1[NB], loss2[NB];
    int wid  = threadIdx.x>>5;
    int lane = threadIdx.x & 31;
    int lr   = lane & 15;
    int b = wid;
    for(int i=lane;i<K2*K2;i+=32) A[b][i] = g_outadj[b*K2*K2+i];
    __syncwarp();
    float diagv = A[b][lr*17];
    float trv = (lane<K2)? diagv : 0.f;
    for(int o=16;o;o>>=1) trv += __shfl_xor_sync(FULL,trv,o);
    if(lane<K2) A[b][lr*17] = 0.f;
    __syncwarp();
    float rsum=0.f;
    for(int l=0;l<K2;l++) rsum += A[b][lr*K2+l];
    float di = 1.f/(sqrtf(fmaxf(rsum,0.f))+EPSL);
    float dinv = (lane<K2)? di : 0.f;
    float cs = 0.f;
    for(int k=0;k<K2;k++){
        float dk = __shfl_sync(FULL,dinv,k);
        cs += A[b][k*K2+lr]*dk;
    }
    cs *= dinv;
    float ov[16];
    #pragma unroll
    for(int l=0;l<16;l++) ov[l] = g_outp[b*K2*HID + l*HID + lane];
    float u1=0.f, osum=0.f;
    #pragma unroll
    for(int l=0;l<16;l++){
        u1   += __shfl_sync(FULL,cs,l)*ov[l];
        osum += ov[l];
    }
    float v = 16.f*r2b[lane];
    #pragma unroll
    for(int c=0;c<32;c++){
        v += __shfl_sync(FULL,u1,c)*r2w[c*HID+lane] + __shfl_sync(FULL,osum,c)*rt2w[c*HID+lane];
    }
    float r = l2b[lane];
    #pragma unroll
    for(int c=0;c<32;c++) r += __shfl_sync(FULL,v,c)*l2w[c*HID+lane];
    r = fmaxf(r, 0.f);
    int lc10 = (lane<COUT)? lane : 0;
    float l3bv = l3b[lc10];
    float lg = (lane<COUT)? l3bv : -1e30f;
    #pragma unroll
    for(int c=0;c<32;c++){
        float rv = __shfl_sync(FULL,r,c);
        lg += rv*l3w[c*COUT+lc10];
    }
    float m = lg;
    for(int o=16;o;o>>=1) m = fmaxf(m, __shfl_xor_sync(FULL,m,o));
    float ez = (lane<COUT)? expf(lg-m) : 0.f;
    float se = ez;
    for(int o=16;o;o>>=1) se += __shfl_xor_sync(FULL,se,o);
    if(lane<COUT && (b*COUT+lane)<out_size) out[b*COUT+lane] = lg - m - logf(se);
    float f = 0.f;
    for(int i=lane;i<K2*K2;i+=32){ float vv=g_SS2[b*K2*K2+i]; f += vv*vv; }
    for(int o=16;o;o>>=1) f += __shfl_xor_sync(FULL,f,o);
    if(lane==0){
        float fro2 = sqrtf(f);
        float fro1 = sqrtf(g_fro2[b]);
        float term1 = (g_sds[b]-g_sas[b])/(g_sds[b]+EPSL);
        float o1b = sqrtf(fmaxf(2.f - 2.f*g_tr1[b]/(fro1*10.f), 0.f));
        float mcb = -(trv/(g_den[b]+EPSL));
        float o2b = sqrtf(fmaxf(2.f - 2.f*g_tr2[b]/(fro2*4.f), 0.f));
        loss1[b] = term1 + o1b;
        loss2[b] = mcb + o2b;
    }
    __syncthreads();
    if(threadIdx.x==0){
        float s1v=0.f, s2v=0.f;
        for(int i=0;i<NB;i++){ s1v+=loss1[i]; s2v+=loss2[i]; }
        if(out_size > NB*COUT)   out[NB*COUT]   = s1v/NB;
        if(out_size > NB*COUT+1) out[NB*COUT+1] = s2v/NB;
    }
    // ---- self-clean (g_cnt handled by edge3) ----
    __syncthreads();
    int tid = threadIdx.x;
    for(int i=tid; i<NB*K2*HID; i+=512) g_outp[i] = 0.f;
    for(int i=tid; i<NB*K2*K2; i+=512){ g_SS2[i]=0.f; g_outadj[i]=0.f; }
    if(tid<NB){
        g_sas[tid]=0.f; g_sds[tid]=0.f; g_tr1[tid]=0.f;
        g_tr2[tid]=0.f; g_den[tid]=0.f; g_fro2[tid]=0.f;
    }
}

// ---------------- launcher: chain A enqueued first; gram chain fills bubbles on s2 ----------------
extern "C" void kernel_launch(void* const* d_in, const int* in_sizes, int n_in,
                              void* d_out, int out_size){
    const float* x    = (const float*)d_in[0];
    const float* l1w  = (const float*)d_in[1];
    const float* l1b  = (const float*)d_in[2];
    const float* p1w  = (const float*)d_in[3];
    const float* p1b  = (const float*)d_in[4];
    const float* p2w  = (const float*)d_in[5];
    const float* p2b  = (const float*)d_in[6];
    const float* c1rw = (const float*)d_in[7];
    const float* c1rb = (const float*)d_in[8];
    const float* c1rt = (const float*)d_in[9];
    const float* c2rw = (const float*)d_in[10];
    const float* c2rb = (const float*)d_in[11];
    const float* c2rt = (const float*)d_in[12];
    const float* l2w  = (const float*)d_in[13];
    const float* l2b  = (const float*)d_in[14];
    const float* l3w  = (const float*)d_in[15];
    const float* l3b  = (const float*)d_in[16];
    const int*   ei   = (const int*)d_in[17];
    const int* src = ei;
    const int* dst = ei + NE;
    float* out = (float*)d_out;

    static cudaStream_t s2 = 0;
    static cudaEvent_t evFork = 0, evJoin = 0;
    if(!s2){
        cudaStreamCreateWithFlags(&s2, cudaStreamNonBlocking);
        cudaEventCreateWithFlags(&evFork, cudaEventDisableTiming);
        cudaEventCreateWithFlags(&evJoin, cudaEventDisableTiming);
    }

    front_kernel<<<1024+2048,256>>>(src, dst, x, l1w, l1b, p1w, p1b);
    cudaEventRecord(evFork, 0);              // fork point: after front only

    // chain A enqueued first -> scheduler priority for the critical path
    edge1_kernel<<<NTOT/8,256>>>();
    mid_kernel<<<NTOT/8,256>>>(c1rw, c1rb, c1rt, p2w, p2b);
    edge3_kernel<<<NTOT/16,256>>>();
    pool_kernel<<<dim3(NB,8),256>>>();

    // chain B on s2, depends only on front; fills SM bubbles
    cudaStreamWaitEvent(s2, evFork, 0);
    gram2_kernel<<<NB*GP_KS,256,0,s2>>>();
    fro_reduce_kernel<<<256,256,0,s2>>>();
    cudaEventRecord(evJoin, s2);

    // join: final needs g_fro2 from the gram chain
    cudaStreamWaitEvent(0, evJoin, 0);
    final_kernel<<<1,512>>>(c2rw, c2rb, c2rt, l2w, l2b, l3w, l3b, out, out_size);
}